// round 2
// baseline (speedup 1.0000x reference)
#include <cuda_runtime.h>

// Problem constants
#define B   16
#define C   16
#define H   256
#define W   256
#define F   32
#define TILE 32     // output tile per block (32x32)
#define FG  8       // filters per block
#define SPITCH 35   // shared input row pitch (odd -> conflict-free pattern)

// packed f32x2 FMA (SASS FFMA2) — only reachable via PTX on sm_103a
__device__ __forceinline__ void fma2(unsigned long long& d,
                                     unsigned long long a,
                                     unsigned long long b) {
    asm("fma.rn.f32x2 %0, %1, %2, %0;" : "+l"(d) : "l"(a), "l"(b));
}
__device__ __forceinline__ unsigned long long pack2(float lo, float hi) {
    unsigned long long p;
    asm("mov.b64 %0, {%1, %2};" : "=l"(p) : "f"(lo), "f"(hi));
    return p;
}
__device__ __forceinline__ void unpack2(unsigned long long p, float& lo, float& hi) {
    asm("mov.b64 {%0, %1}, %2;" : "=f"(lo), "=f"(hi) : "l"(p));
}

__global__ __launch_bounds__(256, 3)
void conv3x3_sig_kernel(const float* __restrict__ x,
                        const float* __restrict__ weights,
                        const float* __restrict__ biases,
                        float* __restrict__ out) {
    // grid: (W/TILE, H/TILE, B * (F/FG))
    const int tx = blockIdx.x;          // tile col
    const int ty = blockIdx.y;          // tile row
    const int b  = blockIdx.z >> 2;     // batch
    const int g  = blockIdx.z & 3;      // filter group (of 4)

    const int tid = threadIdx.x;        // 0..255
    const int row = tid >> 3;           // 0..31 output row within tile
    const int c0  = (tid & 7) * 4;      // output col offset within tile (4 px/thread)

    __shared__ float  s_in[34 * SPITCH];
    __shared__ float2 s_w2[C * 9 * FG]; // weight duplicated pairs: [c][tap][f] = (w,w)

    // ---- stage weights for this filter group (once per block) ----
    // weights layout: [(c*9 + kh*3 + kw) * 32 + f]
    for (int i = tid; i < C * 9 * FG; i += 256) {
        const int c   = i / (9 * FG);
        const int rem = i - c * (9 * FG);
        const int tap = rem >> 3;       // 0..8
        const int f   = rem & 7;
        const float wv = weights[(c * 9 + tap) * F + g * FG + f];
        s_w2[i] = make_float2(wv, wv);
    }

    const int y0 = ty * TILE - 1;       // input tile origin (with pad)
    const int x0 = tx * TILE - 1;

    // accumulators: 8 filters x 2 f32x2 pairs (pixels {0,1} and {2,3})
    unsigned long long acc[FG * 2];
    #pragma unroll
    for (int i = 0; i < FG * 2; i++) acc[i] = 0ull;

    for (int c = 0; c < C; c++) {
        __syncthreads();  // prev compute done (iter0: weights staged)

        // ---- load 34x34 input tile for channel c (zero-padded) ----
        const float* gx = x + ((size_t)(b * C + c) * H) * W;
        #pragma unroll
        for (int i = tid; i < 34 * 34; i += 256) {
            const int r  = i / 34;
            const int cc = i - r * 34;
            const int gy = y0 + r;
            const int gxx = x0 + cc;
            float v = 0.f;
            if ((unsigned)gy < (unsigned)H && (unsigned)gxx < (unsigned)W)
                v = gx[gy * W + gxx];
            s_in[r * SPITCH + cc] = v;
        }
        __syncthreads();

        const unsigned long long* wc =
            reinterpret_cast<const unsigned long long*>(&s_w2[c * 9 * FG]);

        #pragma unroll
        for (int kh = 0; kh < 3; kh++) {
            const float* rp = &s_in[(row + kh) * SPITCH + c0];
            const float v0 = rp[0], v1 = rp[1], v2 = rp[2];
            const float v3 = rp[3], v4 = rp[4], v5 = rp[5];
            const unsigned long long p01 = pack2(v0, v1);
            const unsigned long long p12 = pack2(v1, v2);
            const unsigned long long p23 = pack2(v2, v3);
            const unsigned long long p34 = pack2(v3, v4);
            const unsigned long long p45 = pack2(v4, v5);

            const unsigned long long pa[3] = { p01, p12, p23 };
            const unsigned long long pb[3] = { p23, p34, p45 };

            #pragma unroll
            for (int kw = 0; kw < 3; kw++) {
                const unsigned long long* wt = wc + (kh * 3 + kw) * FG;
                #pragma unroll
                for (int f = 0; f < FG; f++) {
                    const unsigned long long wv = wt[f];   // LDS.64 broadcast
                    fma2(acc[f * 2 + 0], pa[kw], wv);
                    fma2(acc[f * 2 + 1], pb[kw], wv);
                }
            }
        }
    }

    // ---- epilogue: bias + sigmoid + store ----
    const int oy = ty * TILE + row;
    const int ox = tx * TILE + c0;
    #pragma unroll
    for (int f = 0; f < FG; f++) {
        const int fo = g * FG + f;
        float r0, r1, r2, r3;
        unpack2(acc[f * 2 + 0], r0, r1);
        unpack2(acc[f * 2 + 1], r2, r3);

        const float4 bb = *reinterpret_cast<const float4*>(
            &biases[((size_t)fo * H + oy) * W + ox]);
        r0 += bb.x; r1 += bb.y; r2 += bb.z; r3 += bb.w;

        float4 o;
        o.x = 1.f / (1.f + __expf(-r0));
        o.y = 1.f / (1.f + __expf(-r1));
        o.z = 1.f / (1.f + __expf(-r2));
        o.w = 1.f / (1.f + __expf(-r3));

        *reinterpret_cast<float4*>(
            &out[(((size_t)b * F + fo) * H + oy) * W + ox]) = o;
    }
}

extern "C" void kernel_launch(void* const* d_in, const int* in_sizes, int n_in,
                              void* d_out, int out_size) {
    const float* x       = (const float*)d_in[0];
    const float* weights = (const float*)d_in[1];
    const float* biases  = (const float*)d_in[2];
    float* out = (float*)d_out;

    dim3 grid(W / TILE, H / TILE, B * (F / FG));   // (8, 8, 64)
    dim3 block(256);
    conv3x3_sig_kernel<<<grid, block>>>(x, weights, biases, out);
}

// round 3
// speedup vs baseline: 1.1750x; 1.1750x over previous
#include <cuda_runtime.h>

// Problem constants
#define B   16
#define C   16
#define H   256
#define W   256
#define F   32
#define TILE 32     // output tile per block (32x32)
#define FG  8       // filters per block
#define SPITCH 35   // shared input row pitch (conflict-free pattern)

// packed f32x2 FMA (SASS FFMA2) — only reachable via PTX on sm_103a
__device__ __forceinline__ void fma2(unsigned long long& d,
                                     unsigned long long a,
                                     unsigned long long b) {
    asm("fma.rn.f32x2 %0, %1, %2, %0;" : "+l"(d) : "l"(a), "l"(b));
}
__device__ __forceinline__ unsigned long long pack2(float lo, float hi) {
    unsigned long long p;
    asm("mov.b64 %0, {%1, %2};" : "=l"(p) : "f"(lo), "f"(hi));
    return p;
}
__device__ __forceinline__ void unpack2(unsigned long long p, float& lo, float& hi) {
    asm("mov.b64 {%0, %1}, %2;" : "=f"(lo), "=f"(hi) : "l"(p));
}

__global__ __launch_bounds__(256, 3)
void conv3x3_sig_kernel(const float* __restrict__ x,
                        const float* __restrict__ weights,
                        const float* __restrict__ biases,
                        float* __restrict__ out) {
    // grid: (W/TILE, H/TILE, B * (F/FG))
    const int tx = blockIdx.x;          // tile col
    const int ty = blockIdx.y;          // tile row
    const int b  = blockIdx.z >> 2;     // batch
    const int g  = blockIdx.z & 3;      // filter group (of 4)

    const int tid = threadIdx.x;        // 0..255
    const int row = tid >> 3;           // 0..31 output row within tile
    const int c0  = (tid & 7) * 4;      // output col offset within tile (4 px/thread)

    __shared__ float  s_in[2][34 * SPITCH];   // double-buffered input tile
    __shared__ float2 s_w2[C * 9 * FG];       // weight duplicated pairs

    // ---- stage weights for this filter group (once per block) ----
    // weights layout: [(c*9 + kh*3 + kw) * 32 + f]
    for (int i = tid; i < C * 9 * FG; i += 256) {
        const int c   = i / (9 * FG);
        const int rem = i - c * (9 * FG);
        const int tap = rem >> 3;       // 0..8
        const int f   = rem & 7;
        const float wv = weights[(c * 9 + tap) * F + g * FG + f];
        s_w2[i] = make_float2(wv, wv);
    }

    const int y0 = ty * TILE - 1;       // input tile origin (with pad)
    const int x0 = tx * TILE - 1;

    // ---- precompute tile-load geometry (invariant across channels) ----
    int  goff[5];                        // gmem offset within a channel plane
    int  sdst[5];                        // smem slot (-1 => no store)
    bool ldp[5];                         // load predicate (in-bounds)
    #pragma unroll
    for (int i = 0; i < 5; i++) {
        const int idx = tid + 256 * i;
        const bool slot = (idx < 34 * 34);
        const int r  = idx / 34;
        const int cc = idx - r * 34;
        const int gy = y0 + r;
        const int gxx = x0 + cc;
        ldp[i]  = slot && ((unsigned)gy < (unsigned)H) && ((unsigned)gxx < (unsigned)W);
        goff[i] = gy * W + gxx;
        sdst[i] = slot ? (r * SPITCH + cc) : -1;
    }

    const float* gx0 = x + ((size_t)b * C) * H * W;   // channel-0 plane

    // accumulators: 8 filters x 2 f32x2 pairs (pixels {0,1} and {2,3})
    unsigned long long acc[FG * 2];
    #pragma unroll
    for (int i = 0; i < FG * 2; i++) acc[i] = 0ull;

    // ---- prologue: load channel 0 into buffer 0 ----
    {
        float v[5];
        #pragma unroll
        for (int i = 0; i < 5; i++) v[i] = ldp[i] ? gx0[goff[i]] : 0.f;
        #pragma unroll
        for (int i = 0; i < 5; i++) if (sdst[i] >= 0) s_in[0][sdst[i]] = v[i];
    }
    __syncthreads();

    #pragma unroll 2
    for (int c = 0; c < C; c++) {
        const int cur = c & 1;

        // ---- issue next channel's loads early (hide LDG latency) ----
        float nv[5];
        if (c + 1 < C) {
            const float* gn = gx0 + (size_t)(c + 1) * H * W;
            #pragma unroll
            for (int i = 0; i < 5; i++) nv[i] = ldp[i] ? gn[goff[i]] : 0.f;
        }

        // ---- compute channel c from s_in[cur] ----
        const unsigned long long* wc =
            reinterpret_cast<const unsigned long long*>(&s_w2[c * 9 * FG]);

        #pragma unroll
        for (int kh = 0; kh < 3; kh++) {
            const float* rp = &s_in[cur][(row + kh) * SPITCH + c0];
            const float v0 = rp[0], v1 = rp[1], v2 = rp[2];
            const float v3 = rp[3], v4 = rp[4], v5 = rp[5];
            const unsigned long long p01 = pack2(v0, v1);
            const unsigned long long p12 = pack2(v1, v2);
            const unsigned long long p23 = pack2(v2, v3);
            const unsigned long long p34 = pack2(v3, v4);
            const unsigned long long p45 = pack2(v4, v5);

            const unsigned long long pa[3] = { p01, p12, p23 };
            const unsigned long long pb[3] = { p23, p34, p45 };

            #pragma unroll
            for (int kw = 0; kw < 3; kw++) {
                const unsigned long long* wt = wc + (kh * 3 + kw) * FG;
                #pragma unroll
                for (int f = 0; f < FG; f++) {
                    const unsigned long long wv = wt[f];   // LDS.64 broadcast
                    fma2(acc[f * 2 + 0], pa[kw], wv);
                    fma2(acc[f * 2 + 1], pb[kw], wv);
                }
            }
        }

        // ---- store next channel into other buffer ----
        if (c + 1 < C) {
            #pragma unroll
            for (int i = 0; i < 5; i++)
                if (sdst[i] >= 0) s_in[1 - cur][sdst[i]] = nv[i];
        }
        __syncthreads();
    }

    // ---- epilogue: bias + sigmoid + store ----
    const int oy = ty * TILE + row;
    const int ox = tx * TILE + c0;
    #pragma unroll
    for (int f = 0; f < FG; f++) {
        const int fo = g * FG + f;
        float r0, r1, r2, r3;
        unpack2(acc[f * 2 + 0], r0, r1);
        unpack2(acc[f * 2 + 1], r2, r3);

        const float4 bb = *reinterpret_cast<const float4*>(
            &biases[((size_t)fo * H + oy) * W + ox]);
        r0 += bb.x; r1 += bb.y; r2 += bb.z; r3 += bb.w;

        float4 o;
        o.x = 1.f / (1.f + __expf(-r0));
        o.y = 1.f / (1.f + __expf(-r1));
        o.z = 1.f / (1.f + __expf(-r2));
        o.w = 1.f / (1.f + __expf(-r3));

        *reinterpret_cast<float4*>(
            &out[(((size_t)b * F + fo) * H + oy) * W + ox]) = o;
    }
}

extern "C" void kernel_launch(void* const* d_in, const int* in_sizes, int n_in,
                              void* d_out, int out_size) {
    const float* x       = (const float*)d_in[0];
    const float* weights = (const float*)d_in[1];
    const float* biases  = (const float*)d_in[2];
    float* out = (float*)d_out;

    dim3 grid(W / TILE, H / TILE, B * (F / FG));   // (8, 8, 64)
    dim3 block(256);
    conv3x3_sig_kernel<<<grid, block>>>(x, weights, biases, out);
}